// round 9
// baseline (speedup 1.0000x reference)
#include <cuda_runtime.h>
#include <cstdint>
#include <cstddef>

// Problem constants
#define BB 32
#define TT 256
#define DD 512
#define HH 1024
#define GN 4096          // 4*H gate columns
#define MM (BB*TT)       // 8192 rows

#define NBLK 128         // persistent blocks (1/SM, all co-resident)
#define UPB 8            // hidden units per block (x4 gates = 32 cols)
#define PTH 256          // threads in persistent kernel (8 warps, 2/SMSP)

// ---------------- scratch (static device allocations; no cudaMalloc) -------
__device__ float g_zx[(size_t)MM * GN];      // input-projection Z (128 MB)
__device__ float g_h1[(size_t)MM * HH];      // layer-1 hidden history (32 MB)
__device__ float g_hT[2][HH * BB];           // transposed h double buffer [unit][batch]
__device__ unsigned g_flags[NBLK];           // per-block publish counters

// ---------------- f32x2 packed FMA (Blackwell FFMA2) -----------------------
__device__ __forceinline__ float2 ffma2(float2 a, float2 b, float2 c) {
    unsigned long long au = *reinterpret_cast<unsigned long long*>(&a);
    unsigned long long bu = *reinterpret_cast<unsigned long long*>(&b);
    unsigned long long cu = *reinterpret_cast<unsigned long long*>(&c);
    unsigned long long du;
    asm("fma.rn.f32x2 %0, %1, %2, %3;" : "=l"(du) : "l"(au), "l"(bu), "l"(cu));
    return *reinterpret_cast<float2*>(&du);
}

// ---------------- cp.async helpers ------------------------------------------
__device__ __forceinline__ void cp_async16(uint32_t dst_smem, const void* src) {
    asm volatile("cp.async.cg.shared.global [%0], [%1], 16;" :: "r"(dst_smem), "l"(src));
}
__device__ __forceinline__ void cp_commit() {
    asm volatile("cp.async.commit_group;" ::: "memory");
}
template <int N>
__device__ __forceinline__ void cp_wait() {
    asm volatile("cp.async.wait_group %0;" :: "n"(N) : "memory");
}

// wait until the 16 producer blocks of chunk ch have published step `need`
__device__ __forceinline__ void wait_chunk(int ch, unsigned need, int tid) {
    if (tid < 16) {
        const unsigned* f = g_flags + ch * 16 + tid;
        unsigned v;
        do {
            asm volatile("ld.acquire.gpu.global.u32 %0, [%1];"
                         : "=r"(v) : "l"(f) : "memory");
            if (v >= need) break;
            __nanosleep(32);
        } while (true);
    }
}

// ---------------- big time-parallel GEMM: C[M,N] = A[M,K] * B[K,N] ---------
#define GM_BM 128
#define GM_BN 128
#define GM_BK 16

__global__ __launch_bounds__(256, 2) void sgemm_kernel(
    const float* __restrict__ A, const float* __restrict__ B,
    float* __restrict__ C, int M, int N, int K)
{
    __shared__ float As[GM_BK][GM_BM];
    __shared__ float Bs[GM_BK][GM_BN];

    const int tid = threadIdx.x;
    const int m0 = blockIdx.y * GM_BM;
    const int n0 = blockIdx.x * GM_BN;
    const int tx = tid & 15;
    const int ty = tid >> 4;

    float2 acc2[8][4];
#pragma unroll
    for (int i = 0; i < 8; i++)
#pragma unroll
        for (int j = 0; j < 4; j++) acc2[i][j] = make_float2(0.f, 0.f);

    for (int k0 = 0; k0 < K; k0 += GM_BK) {
#pragma unroll
        for (int l = 0; l < 2; ++l) {
            int i = tid + l * 256;
            int row = i >> 2;
            int kq = (i & 3) << 2;
            float4 v = *(const float4*)(A + (size_t)(m0 + row) * K + k0 + kq);
            As[kq + 0][row] = v.x;
            As[kq + 1][row] = v.y;
            As[kq + 2][row] = v.z;
            As[kq + 3][row] = v.w;
        }
#pragma unroll
        for (int l = 0; l < 2; ++l) {
            int i = tid + l * 256;
            int kr = i >> 5;
            int nq = (i & 31) << 2;
            *(float4*)(&Bs[kr][nq]) = *(const float4*)(B + (size_t)(k0 + kr) * N + n0 + nq);
        }
        __syncthreads();

#pragma unroll
        for (int k = 0; k < GM_BK; ++k) {
            float a[8];
            *(float4*)&a[0] = *(const float4*)&As[k][ty * 4];
            *(float4*)&a[4] = *(const float4*)&As[k][64 + ty * 4];
            float4 bv0 = *(const float4*)&Bs[k][tx * 4];
            float4 bv1 = *(const float4*)&Bs[k][64 + tx * 4];
            float2 b2[4];
            b2[0] = make_float2(bv0.x, bv0.y);
            b2[1] = make_float2(bv0.z, bv0.w);
            b2[2] = make_float2(bv1.x, bv1.y);
            b2[3] = make_float2(bv1.z, bv1.w);
#pragma unroll
            for (int i = 0; i < 8; i++) {
                float2 ad = make_float2(a[i], a[i]);
#pragma unroll
                for (int jp = 0; jp < 4; jp++)
                    acc2[i][jp] = ffma2(ad, b2[jp], acc2[i][jp]);
            }
        }
        __syncthreads();
    }

#pragma unroll
    for (int i = 0; i < 8; i++) {
        int row = m0 + ((i < 4) ? (ty * 4 + i) : (64 + ty * 4 + (i - 4)));
        float* cp = C + (size_t)row * N + n0;
        float4 v0 = make_float4(acc2[i][0].x, acc2[i][0].y, acc2[i][1].x, acc2[i][1].y);
        float4 v1 = make_float4(acc2[i][2].x, acc2[i][2].y, acc2[i][3].x, acc2[i][3].y);
        *(float4*)(cp + tx * 4) = v0;
        *(float4*)(cp + 64 + tx * 4) = v1;
    }
}

// ---------------- reset: publish flags + h state ----------------------------
__global__ void reset_kernel() {
    int i = blockIdx.x * blockDim.x + threadIdx.x;
    if (i < NBLK) g_flags[i] = 0u;
    if (i < 2 * HH * BB) ((float*)g_hT)[i] = 0.f;
}

// ---------------- persistent LSTM layer kernel -----------------------------
// 128 blocks x 256 threads. Block bx owns units [bx*8,bx*8+8) x 4 gates.
// Dataflow sync: no global barrier. Block publishes its h slice with a
// per-block release flag; consumers acquire-poll the 16 producer flags of
// each 128-unit chunk just before prefetching it (poll overlapped with the
// in-flight cp.async of the previous chunk). Chunk order rotated per block.
// smem: w_s 128KB | h_s 2x16KB | z_s 2x4.5KB
__global__ __launch_bounds__(PTH, 1) void lstm_persistent(
    const float* __restrict__ Wh,       // [HH][GN] recurrent weights
    const float* __restrict__ zx,       // [MM][GN], row = b*TT + t
    const float* __restrict__ bias,     // [GN]
    float* __restrict__ hist)           // [MM][HH] h history out
{
    extern __shared__ float smem[];
    float* w_s = smem;                           // 32768 floats, pair layout
    float* h_s = smem + 32768;                   // 2 x 4096 floats
    float* z_s = smem + 32768 + 2 * 4096;        // 2 x (32*36)

    const int tid = threadIdx.x;
    const int bx = blockIdx.x;
    const int u0 = bx * UPB;
    const int grp = bx >> 4;             // my chunk group 0..7
    const int cp = tid & 15;             // col pair {2cp, 2cp+1}
    const int bq = (tid >> 4) & 7;       // batch quad 0..7
    const int kh = tid >> 7;             // K half 0/1 (uniform per warp)
    const int gu = tid & 7;              // gate-phase unit
    const int gb = tid >> 3;             // gate-phase batch 0..31

    float* hT = (float*)g_hT;

    // ---- load weight slice into smem, (k-pair, col-pair) layout ----
#pragma unroll 8
    for (int l = 0; l < 128; ++l) {
        int i = tid + l * PTH;           // 0..32767
        int k = i >> 5;
        int cc = i & 31;
        int col = ((cc >> 3) << 10) + u0 + (cc & 7);
        w_s[(k >> 1) * 64 + (cc >> 1) * 4 + (cc & 1) * 2 + (k & 1)] =
            Wh[(size_t)k * GN + col];
    }

    float bi = bias[0 * HH + u0 + gu];
    float bj = bias[1 * HH + u0 + gu];
    float bf = bias[2 * HH + u0 + gu];
    float bo = bias[3 * HH + u0 + gu];

    float creg = 0.f;
    __syncthreads();

    // per-thread chunk-load geometry: 4 float4s/thread/chunk
    const int ld_row = tid >> 3;          // base row 0..31 (stride 32)
    const int ld_c4 = (tid & 7) << 2;     // 0,4,..28

    for (int t = 0; t < TT; ++t) {
        const float* hread = hT + (t & 1) * (HH * BB);
        float* hwrite = hT + ((t + 1) & 1) * (HH * BB);

        // prefetch this step's zx for the gate phase
        const float* zxr = zx + (size_t)(gb * TT + t) * GN + u0 + gu;
        float zxi = __ldg(zxr);
        float zxj = __ldg(zxr + HH);
        float zxf = __ldg(zxr + 2 * HH);
        float zxo = __ldg(zxr + 3 * HH);

        // ---- prologue: first chunk (rotated start) ----
        {
            int cs0 = (grp + 1) & 7;
            if (t > 0) wait_chunk(cs0, (unsigned)t, tid);
            __syncthreads();   // flag ack visible block-wide before loads
            uint32_t dst = (uint32_t)__cvta_generic_to_shared(h_s);
            const float* src = hread + cs0 * 128 * BB;
#pragma unroll
            for (int l = 0; l < 4; ++l) {
                int row = ld_row + l * 32;
                cp_async16(dst + (row * 32 + ld_c4) * 4, src + row * BB + ld_c4);
            }
            cp_commit();
        }

        float2 a00 = make_float2(0.f, 0.f);
        float2 a01 = make_float2(0.f, 0.f);
        float2 a10 = make_float2(0.f, 0.f);
        float2 a11 = make_float2(0.f, 0.f);

#pragma unroll 1
        for (int i = 0; i < 8; ++i) {
            int cs = (grp + 1 + i) & 7;
            if (i < 7) {
                int csn = (grp + 2 + i) & 7;
                if (t > 0) wait_chunk(csn, (unsigned)t, tid);   // poll while chunk i lands
                __syncthreads();   // buffer (i+1)&1 free (compute i-1 done) + flag ack
                float* hb_next = h_s + ((i + 1) & 1) * 4096;
                uint32_t dst = (uint32_t)__cvta_generic_to_shared(hb_next);
                const float* src = hread + csn * 128 * BB;
#pragma unroll
                for (int l = 0; l < 4; ++l) {
                    int row = ld_row + l * 32;
                    cp_async16(dst + (row * 32 + ld_c4) * 4, src + row * BB + ld_c4);
                }
                cp_commit();
                cp_wait<1>();      // chunk i landed
            } else {
                cp_wait<0>();
            }
            __syncthreads();       // chunk i smem visible to all warps

            const float* hb = h_s + (i & 1) * 4096 + kh * 64 * 32;
            const float* wb = w_s + cs * 64 * 64 + kh * 32 * 64;
#pragma unroll 8
            for (int kk2 = 0; kk2 < 32; ++kk2) {
                float4 wv = *(const float4*)(wb + kk2 * 64 + cp * 4);
                float4 h0 = *(const float4*)(hb + (2 * kk2) * 32 + bq * 4);
                float4 h1 = *(const float4*)(hb + (2 * kk2 + 1) * 32 + bq * 4);
                float2 h0lo = make_float2(h0.x, h0.y), h0hi = make_float2(h0.z, h0.w);
                float2 h1lo = make_float2(h1.x, h1.y), h1hi = make_float2(h1.z, h1.w);
                a00 = ffma2(h0lo, make_float2(wv.x, wv.x), a00);
                a01 = ffma2(h0hi, make_float2(wv.x, wv.x), a01);
                a10 = ffma2(h0lo, make_float2(wv.z, wv.z), a10);
                a11 = ffma2(h0hi, make_float2(wv.z, wv.z), a11);
                a00 = ffma2(h1lo, make_float2(wv.y, wv.y), a00);
                a01 = ffma2(h1hi, make_float2(wv.y, wv.y), a01);
                a10 = ffma2(h1lo, make_float2(wv.w, wv.w), a10);
                a11 = ffma2(h1hi, make_float2(wv.w, wv.w), a11);
            }
        }

        // stage partial z to smem (per K-half); z_s free since last step's
        // gate phase ended with a __syncthreads before publish
        float* zh = z_s + kh * (32 * 36);
        *(float4*)(zh + (2 * cp + 0) * 36 + bq * 4) = make_float4(a00.x, a00.y, a01.x, a01.y);
        *(float4*)(zh + (2 * cp + 1) * 36 + bq * 4) = make_float4(a10.x, a10.y, a11.x, a11.y);
        __syncthreads();

        // ---- gate phase: thread = (unit gu, batch gb), combine K halves ----
        {
            float zi = z_s[(0 * 8 + gu) * 36 + gb] + z_s[32 * 36 + (0 * 8 + gu) * 36 + gb] + zxi + bi;
            float zj = z_s[(1 * 8 + gu) * 36 + gb] + z_s[32 * 36 + (1 * 8 + gu) * 36 + gb] + zxj + bj;
            float zf = z_s[(2 * 8 + gu) * 36 + gb] + z_s[32 * 36 + (2 * 8 + gu) * 36 + gb] + zxf + bf;
            float zo = z_s[(3 * 8 + gu) * 36 + gb] + z_s[32 * 36 + (3 * 8 + gu) * 36 + gb] + zxo + bo;

            float ig = 1.f / (1.f + expf(-zi));
            float fg = 1.f / (1.f + expf(-(zf + 1.0f)));   // forget bias 1.0
            float jt = tanhf(zj);
            float cn = fg * creg + ig * jt;
            float og = 1.f / (1.f + expf(-zo));
            float hn = og * tanhf(cn);
            creg = cn;

            hwrite[(u0 + gu) * BB + gb] = hn;
            hist[(size_t)(gb * TT + t) * HH + u0 + gu] = hn;
        }

        __syncthreads();   // all h writes of this block done (also z_s guard)

        // ---- publish: my h slice for step t+1 is ready ----
        if (t < TT - 1 && tid == 0) {
            asm volatile("st.release.gpu.global.u32 [%0], %1;"
                         :: "l"(g_flags + bx), "r"((unsigned)(t + 1)) : "memory");
        }
    }
}

// ---------------- host orchestration ---------------------------------------
extern "C" void kernel_launch(void* const* d_in, const int* in_sizes, int n_in,
                              void* d_out, int out_size)
{
    const float *x = nullptr, *W1 = nullptr, *b1 = nullptr, *W2 = nullptr, *b2 = nullptr;
    for (int i = 0; i < n_in; i++) {
        int s = in_sizes[i];
        const float* p = (const float*)d_in[i];
        if (s == BB * TT * DD) x = p;
        else if (s == (DD + HH) * GN) W1 = p;
        else if (s == (HH + HH) * GN) W2 = p;
        else if (s == GN) { if (!b1) b1 = p; else b2 = p; }
    }
    float* out = (float*)d_out;

    float *zx, *h1;
    { void* p; cudaGetSymbolAddress(&p, g_zx); zx = (float*)p; }
    { void* p; cudaGetSymbolAddress(&p, g_h1); h1 = (float*)p; }

    const int SMEM_BYTES = (32768 + 2 * 4096 + 2 * 32 * 36) * 4;   // ~169.5 KB
    cudaFuncSetAttribute(lstm_persistent,
                         cudaFuncAttributeMaxDynamicSharedMemorySize, SMEM_BYTES);

    dim3 gemm_grid(GN / GM_BN, MM / GM_BM);   // (32, 64)

    // ---- Layer 1 ----
    sgemm_kernel<<<gemm_grid, 256>>>(x, W1, zx, MM, GN, DD);
    reset_kernel<<<(2 * HH * BB + 255) / 256, 256>>>();
    lstm_persistent<<<NBLK, PTH, SMEM_BYTES>>>(W1 + (size_t)DD * GN, zx, b1, h1);

    // ---- Layer 2 ----
    sgemm_kernel<<<gemm_grid, 256>>>(h1, W2, zx, MM, GN, HH);
    reset_kernel<<<(2 * HH * BB + 255) / 256, 256>>>();
    lstm_persistent<<<NBLK, PTH, SMEM_BYTES>>>(W2 + (size_t)HH * GN, zx, b2, out);
}

// round 10
// speedup vs baseline: 1.1891x; 1.1891x over previous
#include <cuda_runtime.h>
#include <cstdint>
#include <cstddef>

// Problem constants
#define BB 32
#define TT 256
#define DD 512
#define HH 1024
#define GN 4096          // 4*H gate columns
#define MM (BB*TT)       // 8192 rows

#define NBLK 128         // persistent blocks (1/SM, all co-resident)
#define UPB 8            // hidden units per block (x4 gates = 32 cols)
#define PTH 256          // threads in persistent kernel (8 warps, 2/SMSP)

// ---------------- scratch (static device allocations; no cudaMalloc) -------
__device__ float g_zx[(size_t)MM * GN];      // input-projection Z (128 MB)
__device__ float g_h1[(size_t)MM * HH];      // layer-1 hidden history (32 MB)
__device__ float g_hT[2][HH * BB];           // transposed h double buffer [unit][batch]
__device__ unsigned g_bar_count;
__device__ unsigned g_bar_phase;

// ---------------- f32x2 packed FMA (Blackwell FFMA2) -----------------------
__device__ __forceinline__ float2 ffma2(float2 a, float2 b, float2 c) {
    unsigned long long au = *reinterpret_cast<unsigned long long*>(&a);
    unsigned long long bu = *reinterpret_cast<unsigned long long*>(&b);
    unsigned long long cu = *reinterpret_cast<unsigned long long*>(&c);
    unsigned long long du;
    asm("fma.rn.f32x2 %0, %1, %2, %3;" : "=l"(du) : "l"(au), "l"(bu), "l"(cu));
    return *reinterpret_cast<float2*>(&du);
}

// ---------------- cp.async helpers ------------------------------------------
__device__ __forceinline__ void cp_async16(uint32_t dst_smem, const void* src) {
    asm volatile("cp.async.cg.shared.global [%0], [%1], 16;" :: "r"(dst_smem), "l"(src));
}
__device__ __forceinline__ void cp_commit() {
    asm volatile("cp.async.commit_group;" ::: "memory");
}
template <int N>
__device__ __forceinline__ void cp_wait() {
    asm volatile("cp.async.wait_group %0;" :: "n"(N) : "memory");
}

// ---------------- big time-parallel GEMM: C[M,N] = A[M,K] * B[K,N] ---------
#define GM_BM 128
#define GM_BN 128
#define GM_BK 16

__global__ __launch_bounds__(256, 2) void sgemm_kernel(
    const float* __restrict__ A, const float* __restrict__ B,
    float* __restrict__ C, int M, int N, int K)
{
    __shared__ float As[GM_BK][GM_BM];
    __shared__ float Bs[GM_BK][GM_BN];

    const int tid = threadIdx.x;
    const int m0 = blockIdx.y * GM_BM;
    const int n0 = blockIdx.x * GM_BN;
    const int tx = tid & 15;
    const int ty = tid >> 4;

    float2 acc2[8][4];
#pragma unroll
    for (int i = 0; i < 8; i++)
#pragma unroll
        for (int j = 0; j < 4; j++) acc2[i][j] = make_float2(0.f, 0.f);

    for (int k0 = 0; k0 < K; k0 += GM_BK) {
#pragma unroll
        for (int l = 0; l < 2; ++l) {
            int i = tid + l * 256;
            int row = i >> 2;
            int kq = (i & 3) << 2;
            float4 v = *(const float4*)(A + (size_t)(m0 + row) * K + k0 + kq);
            As[kq + 0][row] = v.x;
            As[kq + 1][row] = v.y;
            As[kq + 2][row] = v.z;
            As[kq + 3][row] = v.w;
        }
#pragma unroll
        for (int l = 0; l < 2; ++l) {
            int i = tid + l * 256;
            int kr = i >> 5;
            int nq = (i & 31) << 2;
            *(float4*)(&Bs[kr][nq]) = *(const float4*)(B + (size_t)(k0 + kr) * N + n0 + nq);
        }
        __syncthreads();

#pragma unroll
        for (int k = 0; k < GM_BK; ++k) {
            float a[8];
            *(float4*)&a[0] = *(const float4*)&As[k][ty * 4];
            *(float4*)&a[4] = *(const float4*)&As[k][64 + ty * 4];
            float4 bv0 = *(const float4*)&Bs[k][tx * 4];
            float4 bv1 = *(const float4*)&Bs[k][64 + tx * 4];
            float2 b2[4];
            b2[0] = make_float2(bv0.x, bv0.y);
            b2[1] = make_float2(bv0.z, bv0.w);
            b2[2] = make_float2(bv1.x, bv1.y);
            b2[3] = make_float2(bv1.z, bv1.w);
#pragma unroll
            for (int i = 0; i < 8; i++) {
                float2 ad = make_float2(a[i], a[i]);
#pragma unroll
                for (int jp = 0; jp < 4; jp++)
                    acc2[i][jp] = ffma2(ad, b2[jp], acc2[i][jp]);
            }
        }
        __syncthreads();
    }

#pragma unroll
    for (int i = 0; i < 8; i++) {
        int row = m0 + ((i < 4) ? (ty * 4 + i) : (64 + ty * 4 + (i - 4)));
        float* cp = C + (size_t)row * N + n0;
        float4 v0 = make_float4(acc2[i][0].x, acc2[i][0].y, acc2[i][1].x, acc2[i][1].y);
        float4 v1 = make_float4(acc2[i][2].x, acc2[i][2].y, acc2[i][3].x, acc2[i][3].y);
        *(float4*)(cp + tx * 4) = v0;
        *(float4*)(cp + 64 + tx * 4) = v1;
    }
}

// ---------------- reset: barrier counters + h state ------------------------
__global__ void reset_kernel() {
    int i = blockIdx.x * blockDim.x + threadIdx.x;
    if (i == 0) { g_bar_count = 0; g_bar_phase = 0; }
    if (i < 2 * HH * BB) ((float*)g_hT)[i] = 0.f;
}

// ---------------- persistent LSTM layer kernel -----------------------------
// 128 blocks x 256 threads. Block bx owns units [bx*8,bx*8+8) x 4 gates (32
// cols). Thread (cq,bq,kq): cols {4cq..4cq+3} x batches {4bq..4bq+3}, K
// quarter kq (rows [kq*32,kq*32+32) of every 128-k chunk). Per k: 1 LDS.128 w
// (1 wavefront/warp) + 1 LDS.128 h (broadcast, 1 wavefront) -> 8 FFMA2, so
// LDS crossbar at 50% and FMA is the sole bottleneck (8192 cyc/step floor).
// h streamed in 8 double-buffered cp.async chunks; central grid barrier with
// one poller per block.
// smem: w_s 128KB | h_s 2x16KB | z_s 4x4.5KB (~178KB)
__global__ __launch_bounds__(PTH, 1) void lstm_persistent(
    const float* __restrict__ Wh,       // [HH][GN] recurrent weights
    const float* __restrict__ zx,       // [MM][GN], row = b*TT + t
    const float* __restrict__ bias,     // [GN]
    float* __restrict__ hist)           // [MM][HH] h history out
{
    extern __shared__ float smem[];
    float* w_s = smem;                           // [k*32 + col], 32768 floats
    float* h_s = smem + 32768;                   // 2 x 4096 floats
    float* z_s = smem + 32768 + 2 * 4096;        // 4 x (32*36)

    const int tid = threadIdx.x;
    const int u0 = blockIdx.x * UPB;
    const int cq = tid & 7;              // col quad: cols {4cq..4cq+3}
    const int bq = (tid >> 3) & 7;       // batch quad
    const int kq = tid >> 6;             // K quarter 0..3 (uniform per warp)
    const int gu = tid & 7;              // gate-phase unit
    const int gb = tid >> 3;             // gate-phase batch 0..31

    float* hT = (float*)g_hT;

    // ---- load weight slice into smem: w_s[k*32 + cc] ----
#pragma unroll 8
    for (int l = 0; l < 128; ++l) {
        int i = tid + l * PTH;           // 0..32767
        int k = i >> 5;
        int cc = i & 31;
        int col = ((cc >> 3) << 10) + u0 + (cc & 7);
        w_s[i] = Wh[(size_t)k * GN + col];
    }

    float bi = bias[0 * HH + u0 + gu];
    float bj = bias[1 * HH + u0 + gu];
    float bf = bias[2 * HH + u0 + gu];
    float bo = bias[3 * HH + u0 + gu];

    float creg = 0.f;
    __syncthreads();

    // per-thread chunk-load geometry: 4 float4s/thread/chunk
    const int ld_row = tid >> 3;          // base row 0..31 (stride 32)
    const int ld_c4 = (tid & 7) << 2;     // 0,4,..28

    for (int t = 0; t < TT; ++t) {
        const float* hread = hT + (t & 1) * (HH * BB);
        float* hwrite = hT + ((t + 1) & 1) * (HH * BB);

        // prefetch this step's zx for the gate phase
        const float* zxr = zx + (size_t)(gb * TT + t) * GN + u0 + gu;
        float zxi = __ldg(zxr);
        float zxj = __ldg(zxr + HH);
        float zxf = __ldg(zxr + 2 * HH);
        float zxo = __ldg(zxr + 3 * HH);

        // preload chunk 0 into buffer 0
        {
            uint32_t dst = (uint32_t)__cvta_generic_to_shared(h_s);
#pragma unroll
            for (int l = 0; l < 4; ++l) {
                int row = ld_row + l * 32;
                cp_async16(dst + (row * 32 + ld_c4) * 4,
                           hread + row * BB + ld_c4);
            }
            cp_commit();
        }

        // accumulators: 4 cols x (lo,hi) batch pairs
        float2 alo[4], ahi[4];
#pragma unroll
        for (int c = 0; c < 4; ++c) {
            alo[c] = make_float2(0.f, 0.f);
            ahi[c] = make_float2(0.f, 0.f);
        }

#pragma unroll 1
        for (int ch = 0; ch < 8; ++ch) {
            if (ch < 7) {   // prefetch next chunk into other buffer
                float* hb_next = h_s + ((ch + 1) & 1) * 4096;
                uint32_t dst = (uint32_t)__cvta_generic_to_shared(hb_next);
                const float* src = hread + (ch + 1) * 128 * BB;
#pragma unroll
                for (int l = 0; l < 4; ++l) {
                    int row = ld_row + l * 32;
                    cp_async16(dst + (row * 32 + ld_c4) * 4,
                               src + row * BB + ld_c4);
                }
                cp_commit();
                cp_wait<1>();
            } else {
                cp_wait<0>();
            }
            __syncthreads();   // chunk ch visible to all warps

            const float* hb = h_s + (ch & 1) * 4096 + (kq * 32) * 32 + bq * 4;
            const float* wb = w_s + (ch * 128 + kq * 32) * 32 + cq * 4;
#pragma unroll 8
            for (int kk = 0; kk < 32; ++kk) {
                float4 wv = *(const float4*)(wb + kk * 32);
                float4 hv = *(const float4*)(hb + kk * 32);
                float2 hlo = make_float2(hv.x, hv.y);
                float2 hhi = make_float2(hv.z, hv.w);
                alo[0] = ffma2(hlo, make_float2(wv.x, wv.x), alo[0]);
                ahi[0] = ffma2(hhi, make_float2(wv.x, wv.x), ahi[0]);
                alo[1] = ffma2(hlo, make_float2(wv.y, wv.y), alo[1]);
                ahi[1] = ffma2(hhi, make_float2(wv.y, wv.y), ahi[1]);
                alo[2] = ffma2(hlo, make_float2(wv.z, wv.z), alo[2]);
                ahi[2] = ffma2(hhi, make_float2(wv.z, wv.z), ahi[2]);
                alo[3] = ffma2(hlo, make_float2(wv.w, wv.w), alo[3]);
                ahi[3] = ffma2(hhi, make_float2(wv.w, wv.w), ahi[3]);
            }
            __syncthreads();   // free buffer (ch&1) for chunk ch+2 prefetch
        }

        // stage K-quarter partials to smem
        float* zh = z_s + kq * (32 * 36);
#pragma unroll
        for (int c = 0; c < 4; ++c) {
            *(float4*)(zh + (cq * 4 + c) * 36 + bq * 4) =
                make_float4(alo[c].x, alo[c].y, ahi[c].x, ahi[c].y);
        }
        __syncthreads();

        // ---- gate phase: thread = (unit gu, batch gb), combine 4 quarters --
        {
            float zi = zxi + bi, zj = zxj + bj, zf = zxf + bf, zo = zxo + bo;
#pragma unroll
            for (int q = 0; q < 4; ++q) {
                const float* zq = z_s + q * (32 * 36);
                zi += zq[(0 * 8 + gu) * 36 + gb];
                zj += zq[(1 * 8 + gu) * 36 + gb];
                zf += zq[(2 * 8 + gu) * 36 + gb];
                zo += zq[(3 * 8 + gu) * 36 + gb];
            }

            float ig = 1.f / (1.f + expf(-zi));
            float fg = 1.f / (1.f + expf(-(zf + 1.0f)));   // forget bias 1.0
            float jt = tanhf(zj);
            float cn = fg * creg + ig * jt;
            float og = 1.f / (1.f + expf(-zo));
            float hn = og * tanhf(cn);
            creg = cn;

            hwrite[(u0 + gu) * BB + gb] = hn;
            hist[(size_t)(gb * TT + t) * HH + u0 + gu] = hn;
        }

        // ---- central grid barrier, single poller per block ----
        if (t < TT - 1) {
            __syncthreads();   // block's h writes issued (also z_s guard)
            unsigned target = (unsigned)(t + 1);
            if (tid == 0) {
                unsigned prev;
                asm volatile("atom.add.release.gpu.global.u32 %0, [%1], 1;"
                             : "=r"(prev) : "l"(&g_bar_count) : "memory");
                if (prev == NBLK - 1) {
                    g_bar_count = 0;   // ordered by st.release below
                    asm volatile("st.release.gpu.global.u32 [%0], %1;"
                                 :: "l"(&g_bar_phase), "r"(target) : "memory");
                } else {
                    unsigned ph;
                    do {
                        asm volatile("ld.acquire.gpu.global.u32 %0, [%1];"
                                     : "=r"(ph) : "l"(&g_bar_phase) : "memory");
                        if (ph >= target) break;
                        __nanosleep(64);
                    } while (true);
                }
            }
            __syncthreads();
        } else {
            __syncthreads();
        }
    }
}

// ---------------- host orchestration ---------------------------------------
extern "C" void kernel_launch(void* const* d_in, const int* in_sizes, int n_in,
                              void* d_out, int out_size)
{
    const float *x = nullptr, *W1 = nullptr, *b1 = nullptr, *W2 = nullptr, *b2 = nullptr;
    for (int i = 0; i < n_in; i++) {
        int s = in_sizes[i];
        const float* p = (const float*)d_in[i];
        if (s == BB * TT * DD) x = p;
        else if (s == (DD + HH) * GN) W1 = p;
        else if (s == (HH + HH) * GN) W2 = p;
        else if (s == GN) { if (!b1) b1 = p; else b2 = p; }
    }
    float* out = (float*)d_out;

    float *zx, *h1;
    { void* p; cudaGetSymbolAddress(&p, g_zx); zx = (float*)p; }
    { void* p; cudaGetSymbolAddress(&p, g_h1); h1 = (float*)p; }

    const int SMEM_BYTES = (32768 + 2 * 4096 + 4 * 32 * 36) * 4;   // ~182 KB
    cudaFuncSetAttribute(lstm_persistent,
                         cudaFuncAttributeMaxDynamicSharedMemorySize, SMEM_BYTES);

    dim3 gemm_grid(GN / GM_BN, MM / GM_BM);   // (32, 64)

    // ---- Layer 1 ----
    sgemm_kernel<<<gemm_grid, 256>>>(x, W1, zx, MM, GN, DD);
    reset_kernel<<<(2 * HH * BB + 255) / 256, 256>>>();
    lstm_persistent<<<NBLK, PTH, SMEM_BYTES>>>(W1 + (size_t)DD * GN, zx, b1, h1);

    // ---- Layer 2 ----
    sgemm_kernel<<<gemm_grid, 256>>>(h1, W2, zx, MM, GN, HH);
    reset_kernel<<<(2 * HH * BB + 255) / 256, 256>>>();
    lstm_persistent<<<NBLK, PTH, SMEM_BYTES>>>(W2 + (size_t)HH * GN, zx, b2, out);
}